// round 2
// baseline (speedup 1.0000x reference)
#include <cuda_runtime.h>
#include <math.h>
#include <stdint.h>

// Instant-NGP multires hash grid encode, GB300 sm_103a.
// 2M points x 16 levels x 8-corner trilinear gather, FEATURE_DIM=2.
// Levels 0..5 dense (res^3 < 2^19), levels 6..15 hashed (2^19 entries).

#define NUM_LVL   16
#define MAX_ENTRY (1u << 19)
#define HASH_MASK (MAX_ENTRY - 1u)
#define PRIME0 3367900313u
#define PRIME1 2654435761u
#define PRIME2 805459861u
#define DENSE_LEVELS 6   // res: 16,22,30,42,58,80 dense; 111+ hashed (huge margins)

struct LevelParams {
    float scale;   // res - 1.0        (exact in f32)
    float hi;      // (float)(res - 1.0001), matching JAX weak-scalar f32 cast
    int   resi;    // (int)res
    int   pad;
};
struct Params { LevelParams l[NUM_LVL]; };

template <bool DENSE>
__device__ __forceinline__ float2 level_feat(
    float px, float py, float pz,
    const float2* __restrict__ tbl,
    float scale, float hi, int resi)
{
    // to_hash_space + clip (matches clip(x*(res-1), 0, res-1.0001) in f32)
    float cx = fminf(fmaxf(px * scale, 0.0f), hi);
    float cy = fminf(fmaxf(py * scale, 0.0f), hi);
    float cz = fminf(fmaxf(pz * scale, 0.0f), hi);
    float fx = floorf(cx), fy = floorf(cy), fz = floorf(cz);
    int ix = (int)fx, iy = (int)fy, iz = (int)fz;
    float dx = cx - fx, dy = cy - fy, dz = cz - fz;
    float mx = 1.0f - dx, my = 1.0f - dy, mz = 1.0f - dz;

    unsigned idx[8];
    if (DENSE) {
        // idx = cx + cy*res + cz*res^2 (exact integers < 2^24 -> int math is bit-exact)
        int sy = resi;
        int sz = resi * resi;
        int base = ix + iy * sy + iz * sz;
        // corner order c000,c001,c010,c011,c100,c101,c110,c111 (x=bit2,y=bit1,z=bit0)
        idx[0] = base;
        idx[1] = base + sz;
        idx[2] = base + sy;
        idx[3] = base + sy + sz;
        idx[4] = base + 1;
        idx[5] = base + 1 + sz;
        idx[6] = base + 1 + sy;
        idx[7] = base + 1 + sy + sz;
    } else {
        // int64 (x*p0 ^ y*p1 ^ z*p2) mod 2^19  ==  low-19-bits of uint32 math
        unsigned hx0 = (unsigned)ix * PRIME0, hx1 = hx0 + PRIME0;
        unsigned hy0 = (unsigned)iy * PRIME1, hy1 = hy0 + PRIME1;
        unsigned hz0 = (unsigned)iz * PRIME2, hz1 = hz0 + PRIME2;
        idx[0] = (hx0 ^ hy0 ^ hz0) & HASH_MASK;
        idx[1] = (hx0 ^ hy0 ^ hz1) & HASH_MASK;
        idx[2] = (hx0 ^ hy1 ^ hz0) & HASH_MASK;
        idx[3] = (hx0 ^ hy1 ^ hz1) & HASH_MASK;
        idx[4] = (hx1 ^ hy0 ^ hz0) & HASH_MASK;
        idx[5] = (hx1 ^ hy0 ^ hz1) & HASH_MASK;
        idx[6] = (hx1 ^ hy1 ^ hz0) & HASH_MASK;
        idx[7] = (hx1 ^ hy1 ^ hz1) & HASH_MASK;
    }

    // issue all 8 gathers back-to-back for MLP, then interpolate
    float2 f[8];
#pragma unroll
    for (int c = 0; c < 8; c++) f[c] = __ldg(tbl + idx[c]);

    float wx[2] = {mx, dx};
    float wy[2] = {my, dy};
    float wz[2] = {mz, dz};
    float r0 = 0.0f, r1 = 0.0f;
#pragma unroll
    for (int c = 0; c < 8; c++) {
        float w = wx[(c >> 2) & 1] * wy[(c >> 1) & 1] * wz[c & 1];
        r0 = fmaf(f[c].x, w, r0);
        r1 = fmaf(f[c].y, w, r1);
    }
    return make_float2(r0, r1);
}

__global__ __launch_bounds__(256)
void grid_encode_kernel(const float* __restrict__ x,
                        const float* __restrict__ tables,
                        float4* __restrict__ out,
                        int n, Params P)
{
    int i = blockIdx.x * blockDim.x + threadIdx.x;
    if (i >= n) return;

    float px = __ldg(x + 3 * i + 0);
    float py = __ldg(x + 3 * i + 1);
    float pz = __ldg(x + 3 * i + 2);

    const float2* tb = (const float2*)tables;

#pragma unroll
    for (int l = 0; l < NUM_LVL; l += 2) {
        float2 a, b;
        {
            const float2* t = tb + (size_t)l * MAX_ENTRY;
            if (l < DENSE_LEVELS)
                a = level_feat<true >(px, py, pz, t, P.l[l].scale, P.l[l].hi, P.l[l].resi);
            else
                a = level_feat<false>(px, py, pz, t, P.l[l].scale, P.l[l].hi, P.l[l].resi);
        }
        {
            const int l1 = l + 1;
            const float2* t = tb + (size_t)l1 * MAX_ENTRY;
            if (l1 < DENSE_LEVELS)
                b = level_feat<true >(px, py, pz, t, P.l[l1].scale, P.l[l1].hi, P.l[l1].resi);
            else
                b = level_feat<false>(px, py, pz, t, P.l[l1].scale, P.l[l1].hi, P.l[l1].resi);
        }
        // Streaming store: output is write-once, never re-read; evict-first
        // keeps L2 capacity for the 64MB tables + gather working set.
        __stcs(&out[(size_t)i * 8 + (l >> 1)], make_float4(a.x, a.y, b.x, b.y));
    }
}

extern "C" void kernel_launch(void* const* d_in, const int* in_sizes, int n_in,
                              void* d_out, int out_size)
{
    const float* x      = (const float*)d_in[0];
    const float* tables = (const float*)d_in[1];
    float*       out    = (float*)d_out;
    int n = in_sizes[0] / 3;

    // Compute per-level constants with the EXACT double-precision ops the
    // reference uses (same host, same libm): b = exp((log(2048)-log(16))/15),
    // res_i = floor(16 * b**i). Level 15 sits within ~3e-12 of 2048.0, so
    // hardcoding would risk an off-by-one resolution; recomputing matches.
    Params P;
    double b = exp((log(2048.0) - log(16.0)) / 15.0);
    for (int i = 0; i < NUM_LVL; i++) {
        double r = floor(16.0 * pow(b, (double)i));
        P.l[i].scale = (float)(r - 1.0);
        P.l[i].hi    = (float)(r - 1.0001);
        P.l[i].resi  = (int)r;
        P.l[i].pad   = 0;
    }

    int block = 256;
    int grid  = (n + block - 1) / block;
    grid_encode_kernel<<<grid, block>>>(x, tables, (float4*)out, n, P);
}

// round 4
// speedup vs baseline: 1.1031x; 1.1031x over previous
#include <cuda_runtime.h>
#include <math.h>
#include <stdint.h>

// Instant-NGP multires hash grid encode, GB300 sm_103a.
// 2M points x 16 levels x 8-corner trilinear gather, FEATURE_DIM=2.
// Levels 0,1 dense from SHARED MEMORY (118KB preload); levels 2..5 dense from
// gmem with parity-merged float4 pair loads; levels 6..15 hashed (2^19).

#define NUM_LVL   16
#define MAX_ENTRY (1u << 19)
#define HASH_MASK (MAX_ENTRY - 1u)
#define PRIME0 3367900313u
#define PRIME1 2654435761u
#define PRIME2 805459861u

#define L0_ENTRIES 4096     // 16^3
#define L1_ENTRIES 10648    // 22^3
#define SMEM_ENTRIES (L0_ENTRIES + L1_ENTRIES)   // 14744 float2 = 117,952 B
#define BLOCK 1024

struct LevelParams {
    float scale;   // res - 1.0
    float hi;      // (float)(res - 1.0001)
    int   resi;
    int   pad;
};
struct Params { LevelParams l[NUM_LVL]; };

// ---------- shared helpers ----------
struct Corner {
    int ix, iy, iz;
    float dx, dy, dz, mx, my, mz;
};

__device__ __forceinline__ Corner corner_of(float px, float py, float pz,
                                            float scale, float hi)
{
    Corner c;
    float cx = fminf(fmaxf(px * scale, 0.0f), hi);
    float cy = fminf(fmaxf(py * scale, 0.0f), hi);
    float cz = fminf(fmaxf(pz * scale, 0.0f), hi);
    float fx = floorf(cx), fy = floorf(cy), fz = floorf(cz);
    c.ix = (int)fx; c.iy = (int)fy; c.iz = (int)fz;
    c.dx = cx - fx; c.dy = cy - fy; c.dz = cz - fz;
    c.mx = 1.0f - c.dx; c.my = 1.0f - c.dy; c.mz = 1.0f - c.dz;
    return c;
}

// corner order c000..c111 with x=bit2, y=bit1, z=bit0 (matches OFFSETS)
__device__ __forceinline__ float2 interp8(const float2 f[8], const Corner& c)
{
    float wx[2] = {c.mx, c.dx};
    float wy[2] = {c.my, c.dy};
    float wz[2] = {c.mz, c.dz};
    float r0 = 0.0f, r1 = 0.0f;
#pragma unroll
    for (int k = 0; k < 8; k++) {
        float w = wx[(k >> 2) & 1] * wy[(k >> 1) & 1] * wz[k & 1];
        r0 = fmaf(f[k].x, w, r0);
        r1 = fmaf(f[k].y, w, r1);
    }
    return make_float2(r0, r1);
}

// ---------- level kernels ----------
// Dense level served from shared memory (levels 0,1).
__device__ __forceinline__ float2 level_smem(float px, float py, float pz,
                                             const float2* s_tab,
                                             float scale, float hi, int resi)
{
    Corner c = corner_of(px, py, pz, scale, hi);
    int sy = resi, sz = resi * resi;
    int base = c.ix + c.iy * sy + c.iz * sz;
    float2 f[8];
    f[0] = s_tab[base];
    f[4] = s_tab[base + 1];
    f[2] = s_tab[base + sy];
    f[6] = s_tab[base + sy + 1];
    f[1] = s_tab[base + sz];
    f[5] = s_tab[base + sz + 1];
    f[3] = s_tab[base + sy + sz];
    f[7] = s_tab[base + sy + sz + 1];
    return interp8(f, c);
}

// Dense level from gmem; all dense res are EVEN so the four x-pairs
// (stride-1 adjacent float2s) share the parity of base -> merged float4 loads
// when base is even (halves L1tex wavefronts for those lanes).
__device__ __forceinline__ float2 level_dense_g(float px, float py, float pz,
                                                const float2* __restrict__ tbl,
                                                float scale, float hi, int resi)
{
    Corner c = corner_of(px, py, pz, scale, hi);
    int sy = resi, sz = resi * resi;
    int base = c.ix + c.iy * sy + c.iz * sz;
    float2 f[8];
    if ((base & 1) == 0) {
        float4 q0 = __ldg((const float4*)(tbl + base));
        float4 q1 = __ldg((const float4*)(tbl + base + sy));
        float4 q2 = __ldg((const float4*)(tbl + base + sz));
        float4 q3 = __ldg((const float4*)(tbl + base + sy + sz));
        f[0] = make_float2(q0.x, q0.y); f[4] = make_float2(q0.z, q0.w);
        f[2] = make_float2(q1.x, q1.y); f[6] = make_float2(q1.z, q1.w);
        f[1] = make_float2(q2.x, q2.y); f[5] = make_float2(q2.z, q2.w);
        f[3] = make_float2(q3.x, q3.y); f[7] = make_float2(q3.z, q3.w);
    } else {
        f[0] = __ldg(tbl + base);
        f[4] = __ldg(tbl + base + 1);
        f[2] = __ldg(tbl + base + sy);
        f[6] = __ldg(tbl + base + sy + 1);
        f[1] = __ldg(tbl + base + sz);
        f[5] = __ldg(tbl + base + sz + 1);
        f[3] = __ldg(tbl + base + sy + sz);
        f[7] = __ldg(tbl + base + sy + sz + 1);
    }
    return interp8(f, c);
}

// Hashed level (levels 6..15). uint32 mul/xor/mask is bit-exact vs int64 mod 2^19.
__device__ __forceinline__ float2 level_hash(float px, float py, float pz,
                                             const float2* __restrict__ tbl,
                                             float scale, float hi)
{
    Corner c = corner_of(px, py, pz, scale, hi);
    unsigned hx0 = (unsigned)c.ix * PRIME0, hx1 = hx0 + PRIME0;
    unsigned hy0 = (unsigned)c.iy * PRIME1, hy1 = hy0 + PRIME1;
    unsigned hz0 = (unsigned)c.iz * PRIME2, hz1 = hz0 + PRIME2;
    float2 f[8];
    f[0] = __ldg(tbl + ((hx0 ^ hy0 ^ hz0) & HASH_MASK));
    f[1] = __ldg(tbl + ((hx0 ^ hy0 ^ hz1) & HASH_MASK));
    f[2] = __ldg(tbl + ((hx0 ^ hy1 ^ hz0) & HASH_MASK));
    f[3] = __ldg(tbl + ((hx0 ^ hy1 ^ hz1) & HASH_MASK));
    f[4] = __ldg(tbl + ((hx1 ^ hy0 ^ hz0) & HASH_MASK));
    f[5] = __ldg(tbl + ((hx1 ^ hy0 ^ hz1) & HASH_MASK));
    f[6] = __ldg(tbl + ((hx1 ^ hy1 ^ hz0) & HASH_MASK));
    f[7] = __ldg(tbl + ((hx1 ^ hy1 ^ hz1) & HASH_MASK));
    return interp8(f, c);
}

__global__ __launch_bounds__(BLOCK, 1)
void grid_encode_kernel(const float* __restrict__ x,
                        const float* __restrict__ tables,
                        float4* __restrict__ out,
                        int n, Params P)
{
    extern __shared__ float2 s_tab[];   // [SMEM_ENTRIES]
    const float2* tb = (const float2*)tables;

    // cooperative preload of levels 0 and 1 (bit-exact copy)
    for (int j = threadIdx.x; j < SMEM_ENTRIES; j += BLOCK) {
        s_tab[j] = (j < L0_ENTRIES) ? tb[j]
                                    : tb[MAX_ENTRY + (unsigned)(j - L0_ENTRIES)];
    }
    __syncthreads();

    const float2* s_l0 = s_tab;
    const float2* s_l1 = s_tab + L0_ENTRIES;

    for (int i = blockIdx.x * BLOCK + threadIdx.x; i < n;
         i += gridDim.x * BLOCK)
    {
        float px = __ldg(x + 3 * i + 0);
        float py = __ldg(x + 3 * i + 1);
        float pz = __ldg(x + 3 * i + 2);

        float2 r[NUM_LVL];
        r[0] = level_smem(px, py, pz, s_l0, P.l[0].scale, P.l[0].hi, P.l[0].resi);
        r[1] = level_smem(px, py, pz, s_l1, P.l[1].scale, P.l[1].hi, P.l[1].resi);
#pragma unroll
        for (int l = 2; l < 6; l++)
            r[l] = level_dense_g(px, py, pz, tb + (size_t)l * MAX_ENTRY,
                                 P.l[l].scale, P.l[l].hi, P.l[l].resi);
#pragma unroll
        for (int l = 6; l < NUM_LVL; l++)
            r[l] = level_hash(px, py, pz, tb + (size_t)l * MAX_ENTRY,
                              P.l[l].scale, P.l[l].hi);

#pragma unroll
        for (int p = 0; p < 8; p++) {
            // streaming store: output is write-once, keep L2 for the tables
            __stcs(&out[(size_t)i * 8 + p],
                   make_float4(r[2*p].x, r[2*p].y, r[2*p+1].x, r[2*p+1].y));
        }
    }
}

extern "C" void kernel_launch(void* const* d_in, const int* in_sizes, int n_in,
                              void* d_out, int out_size)
{
    const float* x      = (const float*)d_in[0];
    const float* tables = (const float*)d_in[1];
    float*       out    = (float*)d_out;
    int n = in_sizes[0] / 3;

    // Per-level constants with the exact double-precision ops the reference
    // uses (same libm): b = exp((log(2048)-log(16))/15), res_i = floor(16*b^i).
    Params P;
    double b = exp((log(2048.0) - log(16.0)) / 15.0);
    for (int i = 0; i < NUM_LVL; i++) {
        double r = floor(16.0 * pow(b, (double)i));
        P.l[i].scale = (float)(r - 1.0);
        P.l[i].hi    = (float)(r - 1.0001);
        P.l[i].resi  = (int)r;
        P.l[i].pad   = 0;
    }

    static int smem_set = 0;
    const int smem_bytes = SMEM_ENTRIES * sizeof(float2);   // 117,952 B
    if (!smem_set) {
        cudaFuncSetAttribute(grid_encode_kernel,
                             cudaFuncAttributeMaxDynamicSharedMemorySize,
                             smem_bytes);
        smem_set = 1;
    }

    int num_sms = 148;
    cudaDeviceGetAttribute(&num_sms, cudaDevAttrMultiProcessorCount, 0);

    // Persistent-ish: 1 CTA/SM (smem-limited anyway); each CTA loads the
    // shared tables once and grid-strides over points.
    int grid = num_sms;
    int max_grid = (n + BLOCK - 1) / BLOCK;
    if (grid > max_grid) grid = max_grid;

    grid_encode_kernel<<<grid, BLOCK, smem_bytes>>>(x, tables, (float4*)out, n, P);
}